// round 3
// baseline (speedup 1.0000x reference)
#include <cuda_runtime.h>
#include <math.h>

// ---------------------------------------------------------------------------
// MultiHeadCrossAttentionBlock: B=4, S=2048, D=512, H=8, DK=64
// d_out = out [B,S,D] ++ attn.mean(axis=1) [B,S,S]  (floats, concatenated)
//
// Round 2: fused attention. No P matrix in global memory. Per (b, q-tile)
// block loops over all 8 heads: QK^T -> softmax (smem) -> mean RMW -> P@V.
// Full fp32 FMA everywhere (softmax is near-argmax at score sigma ~512;
// low-precision scores flip argmaxes and blow up rel_err).
// ---------------------------------------------------------------------------

namespace cfg {
constexpr int B  = 4;
constexpr int S  = 2048;
constexpr int D  = 512;
constexpr int H  = 8;
constexpr int DK = 64;
constexpr int N3 = 3 * D;          // 1536
constexpr int MROWS = B * S;       // 8192
constexpr float SCALE = 0.125f;    // DK^-0.5
constexpr int TQ = 16;             // q rows per block
constexpr int TK = 256;            // k chunk (K^T and V chunks share a buffer)
// dynamic smem: Ss[TQ][S] + KVs[DK*TK] + Qs[DK][20]
constexpr int SMEM2_FLOATS = TQ * S + DK * TK + DK * 20;
constexpr int SMEM2 = SMEM2_FLOATS * 4;   // 201,728 bytes
}

// ------------------------------ scratch (64 MB total) ----------------------
__device__ float g_Q [cfg::B * cfg::H * cfg::S * cfg::DK];   // [b,h,s,dk]
__device__ float g_Kt[cfg::B * cfg::H * cfg::DK * cfg::S];   // [b,h,dk,s]
__device__ float g_V [cfg::B * cfg::H * cfg::S * cfg::DK];   // [b,h,s,dk]
__device__ float g_ctx[cfg::B * cfg::S * cfg::D];            // [b,s,h*DK+dk]

// ---------------------------------------------------------------------------
// K1: QKV projection. C[8192,1536] = Z @ Wqkv  (Z = Zq for n<512, else Zkv)
// 128x128x16 tiles, 256 threads, 8x8 micro-tile.
// ---------------------------------------------------------------------------
__global__ __launch_bounds__(256) void k1_qkv(
    const float* __restrict__ Zq, const float* __restrict__ Zkv,
    const float* __restrict__ W)
{
    using namespace cfg;
    constexpr int BM = 128, BN = 128, BK = 16;
    __shared__ float As[BK][BM + 4];
    __shared__ float Bs[BK][BN];

    const int row0 = blockIdx.x * BM;
    const int col0 = blockIdx.y * BN;
    const float* __restrict__ Z = (col0 < D) ? Zq : Zkv;

    const int t  = threadIdx.x;
    const int tm = (t >> 4) << 3;
    const int tn = (t & 15) << 3;

    float acc[8][8];
#pragma unroll
    for (int i = 0; i < 8; i++)
#pragma unroll
        for (int j = 0; j < 8; j++) acc[i][j] = 0.f;

    for (int k0 = 0; k0 < D; k0 += BK) {
#pragma unroll
        for (int i = 0; i < 8; i++) {           // A tile: 128x16
            int p = t + i * 256;
            int m = p >> 4, k = p & 15;
            As[k][m] = Z[(size_t)(row0 + m) * D + k0 + k];
        }
#pragma unroll
        for (int i = 0; i < 8; i++) {           // B tile: 16x128
            int p = t + i * 256;
            int k = p >> 7, n = p & 127;
            Bs[k][n] = W[(size_t)(k0 + k) * N3 + col0 + n];
        }
        __syncthreads();
#pragma unroll
        for (int k = 0; k < BK; k++) {
            float a[8], b[8];
#pragma unroll
            for (int i = 0; i < 8; i++) a[i] = As[k][tm + i];
#pragma unroll
            for (int j = 0; j < 8; j++) b[j] = Bs[k][tn + j];
#pragma unroll
            for (int i = 0; i < 8; i++)
#pragma unroll
                for (int j = 0; j < 8; j++)
                    acc[i][j] = fmaf(a[i], b[j], acc[i][j]);
        }
        __syncthreads();
    }

    const int part = col0 / D;                  // 0=Q, 1=K, 2=V (block-uniform)
#pragma unroll
    for (int i = 0; i < 8; i++) {
        const int r = row0 + tm + i;
        const int b = r >> 11, s = r & (S - 1);
#pragma unroll
        for (int j = 0; j < 8; j++) {
            const int c  = col0 + tn + j - part * D;
            const int h  = c >> 6, dk = c & 63;
            const float v = acc[i][j];
            if (part == 0)      g_Q [((size_t)(b * H + h) * S  + s)  * DK + dk] = v;
            else if (part == 1) g_Kt[((size_t)(b * H + h) * DK + dk) * S  + s ] = v;
            else                g_V [((size_t)(b * H + h) * S  + s)  * DK + dk] = v;
        }
    }
}

// ---------------------------------------------------------------------------
// K2: fused attention. Grid (S/TQ=128, B=4), 256 threads, 197 KB dyn smem.
// Per block: loop h=0..7 { scores -> softmax -> attn_mean RMW -> ctx=P@V }.
// The (b, q-tile) attn_mean rows are touched by exactly ONE block => the
// global read-modify-write across the h loop is race-free.
// ---------------------------------------------------------------------------
__global__ __launch_bounds__(256) void k2_attn(
    const float* __restrict__ mask, float* __restrict__ attn_out)
{
    using namespace cfg;
    extern __shared__ float sm[];
    float* Ss  = sm;                      // [TQ][S]     scores / probs
    float* KVs = Ss + TQ * S;             // [DK][TK] K^T chunk, then [TK][DK] V chunk
    float* Qs  = KVs + DK * TK;           // [DK][20]    d-major Q tile (padded)

    const int qt = blockIdx.x;
    const int b  = blockIdx.y;
    const int q0 = qt * TQ;
    const int t  = threadIdx.x;

    for (int h = 0; h < H; h++) {
        const int bh = b * H + h;
        const float* __restrict__ Qg  = g_Q  + ((size_t)bh * S + q0) * DK;
        const float* __restrict__ Ktg = g_Kt + (size_t)bh * DK * S;
        const float* __restrict__ Vg  = g_V  + (size_t)bh * S * DK;

        // ---- Q tile transposed into smem (16x64 -> [d][q]) ----
        // (first __syncthreads inside the kc loop orders this vs. readers,
        //  and orders the new head's smem writes vs. the previous head's PV)
#pragma unroll
        for (int i = 0; i < 4; i++) {
            int p = t + i * 256;
            int q = p >> 6, d = p & 63;
            Qs[d * 20 + q] = Qg[q * DK + d];
        }

        // ---- scores: thread (qi=t/64, ki=t%64) owns 4q x 4k per 256-k chunk
        const int qi = t >> 6;
        const int ki = t & 63;
        for (int kc = 0; kc < S; kc += TK) {
            __syncthreads();
#pragma unroll
            for (int i = 0; i < 16; i++) {        // K chunk [DK][TK], d-major
                int p4 = t + i * 256;
                int d = p4 >> 6, k4 = p4 & 63;
                float4 v = *(const float4*)&Ktg[(size_t)d * S + kc + (k4 << 2)];
                *(float4*)&KVs[d * TK + (k4 << 2)] = v;
            }
            __syncthreads();

            float acc[4][4];
#pragma unroll
            for (int i = 0; i < 4; i++)
#pragma unroll
                for (int j = 0; j < 4; j++) acc[i][j] = 0.f;

#pragma unroll
            for (int d = 0; d < DK; d++) {
                const float4 kv = *(const float4*)&KVs[d * TK + (ki << 2)];
                const float a0 = Qs[d * 20 + (qi << 2) + 0];
                const float a1 = Qs[d * 20 + (qi << 2) + 1];
                const float a2 = Qs[d * 20 + (qi << 2) + 2];
                const float a3 = Qs[d * 20 + (qi << 2) + 3];
                acc[0][0] = fmaf(a0, kv.x, acc[0][0]);
                acc[0][1] = fmaf(a0, kv.y, acc[0][1]);
                acc[0][2] = fmaf(a0, kv.z, acc[0][2]);
                acc[0][3] = fmaf(a0, kv.w, acc[0][3]);
                acc[1][0] = fmaf(a1, kv.x, acc[1][0]);
                acc[1][1] = fmaf(a1, kv.y, acc[1][1]);
                acc[1][2] = fmaf(a1, kv.z, acc[1][2]);
                acc[1][3] = fmaf(a1, kv.w, acc[1][3]);
                acc[2][0] = fmaf(a2, kv.x, acc[2][0]);
                acc[2][1] = fmaf(a2, kv.y, acc[2][1]);
                acc[2][2] = fmaf(a2, kv.z, acc[2][2]);
                acc[2][3] = fmaf(a2, kv.w, acc[2][3]);
                acc[3][0] = fmaf(a3, kv.x, acc[3][0]);
                acc[3][1] = fmaf(a3, kv.y, acc[3][1]);
                acc[3][2] = fmaf(a3, kv.z, acc[3][2]);
                acc[3][3] = fmaf(a3, kv.w, acc[3][3]);
            }

#pragma unroll
            for (int i = 0; i < 4; i++) {         // scores*scale + mask -> Ss
                const int q = (qi << 2) + i;
                const float4 mk = *(const float4*)&mask[(size_t)(q0 + q) * S + kc + (ki << 2)];
                float4 o;
                o.x = fmaf(acc[i][0], SCALE, mk.x);
                o.y = fmaf(acc[i][1], SCALE, mk.y);
                o.z = fmaf(acc[i][2], SCALE, mk.z);
                o.w = fmaf(acc[i][3], SCALE, mk.w);
                *(float4*)&Ss[q * S + kc + (ki << 2)] = o;
            }
        }
        __syncthreads();

        // ---- softmax + attn_mean RMW: warp w handles rows 2w, 2w+1 ----
        const int w = t >> 5, lane = t & 31;
#pragma unroll
        for (int rr = 0; rr < 2; rr++) {
            const int q = w * 2 + rr;
            float* row = Ss + q * S;
            float m = -1e30f;
            for (int i = lane; i < S; i += 32) m = fmaxf(m, row[i]);
#pragma unroll
            for (int o = 16; o; o >>= 1) m = fmaxf(m, __shfl_xor_sync(0xFFFFFFFFu, m, o));
            float l = 0.f;
            for (int i = lane; i < S; i += 32) {
                float e = __expf(row[i] - m);
                row[i] = e;
                l += e;
            }
#pragma unroll
            for (int o = 16; o; o >>= 1) l += __shfl_xor_sync(0xFFFFFFFFu, l, o);
            const float inv = 1.f / l;

            float* __restrict__ arow = attn_out + ((size_t)b * S + q0 + q) * S;
            for (int i = lane * 4; i < S; i += 128) {
                float4 e = *(float4*)&row[i];
                e.x *= inv; e.y *= inv; e.z *= inv; e.w *= inv;
                *(float4*)&row[i] = e;                 // normalized P back to smem
                float4 a;
                a.x = e.x * 0.125f; a.y = e.y * 0.125f;
                a.z = e.z * 0.125f; a.w = e.w * 0.125f;
                if (h > 0) {
                    float4 prev = *(float4*)&arow[i];
                    a.x += prev.x; a.y += prev.y; a.z += prev.z; a.w += prev.w;
                }
                *(float4*)&arow[i] = a;
            }
        }
        __syncthreads();

        // ---- ctx = P @ V : thread (q=t/16, ng=t%16) owns ctx[q][4n] ----
        const int pq = t >> 4;
        const int ng = t & 15;
        float4 cacc = make_float4(0.f, 0.f, 0.f, 0.f);

        for (int vc = 0; vc < S; vc += TK) {
#pragma unroll
            for (int i = 0; i < 16; i++) {        // V chunk [TK][DK]
                int p4 = t + i * 256;
                int k = p4 >> 4, n4 = p4 & 15;
                float4 v = *(const float4*)&Vg[(size_t)(vc + k) * DK + (n4 << 2)];
                *(float4*)&KVs[k * DK + (n4 << 2)] = v;
            }
            __syncthreads();
#pragma unroll 8
            for (int k0 = 0; k0 < TK; k0 += 4) {
                const float4 p = *(const float4*)&Ss[pq * S + vc + k0];
                const float4 v0 = *(const float4*)&KVs[(k0 + 0) * DK + (ng << 2)];
                const float4 v1 = *(const float4*)&KVs[(k0 + 1) * DK + (ng << 2)];
                const float4 v2 = *(const float4*)&KVs[(k0 + 2) * DK + (ng << 2)];
                const float4 v3 = *(const float4*)&KVs[(k0 + 3) * DK + (ng << 2)];
                cacc.x = fmaf(p.x, v0.x, cacc.x);
                cacc.y = fmaf(p.x, v0.y, cacc.y);
                cacc.z = fmaf(p.x, v0.z, cacc.z);
                cacc.w = fmaf(p.x, v0.w, cacc.w);
                cacc.x = fmaf(p.y, v1.x, cacc.x);
                cacc.y = fmaf(p.y, v1.y, cacc.y);
                cacc.z = fmaf(p.y, v1.z, cacc.z);
                cacc.w = fmaf(p.y, v1.w, cacc.w);
                cacc.x = fmaf(p.z, v2.x, cacc.x);
                cacc.y = fmaf(p.z, v2.y, cacc.y);
                cacc.z = fmaf(p.z, v2.z, cacc.z);
                cacc.w = fmaf(p.z, v2.w, cacc.w);
                cacc.x = fmaf(p.w, v3.x, cacc.x);
                cacc.y = fmaf(p.w, v3.y, cacc.y);
                cacc.z = fmaf(p.w, v3.z, cacc.z);
                cacc.w = fmaf(p.w, v3.w, cacc.w);
            }
            __syncthreads();
        }
        *(float4*)&g_ctx[((size_t)b * S + q0 + pq) * D + h * DK + (ng << 2)] = cacc;
        // loop-top __syncthreads (inside next head's kc loop) orders reuse
    }
}

// ---------------------------------------------------------------------------
// K5: out[8192,512] = ctx @ Wout.  Same scheme as K1.
// ---------------------------------------------------------------------------
__global__ __launch_bounds__(256) void k5_out(
    const float* __restrict__ Wout, float* __restrict__ out)
{
    using namespace cfg;
    constexpr int BM = 128, BN = 128, BK = 16;
    __shared__ float As[BK][BM + 4];
    __shared__ float Bs[BK][BN];

    const int row0 = blockIdx.x * BM;
    const int col0 = blockIdx.y * BN;
    const int t  = threadIdx.x;
    const int tm = (t >> 4) << 3;
    const int tn = (t & 15) << 3;

    float acc[8][8];
#pragma unroll
    for (int i = 0; i < 8; i++)
#pragma unroll
        for (int j = 0; j < 8; j++) acc[i][j] = 0.f;

    for (int k0 = 0; k0 < D; k0 += BK) {
#pragma unroll
        for (int i = 0; i < 8; i++) {
            int p = t + i * 256;
            int m = p >> 4, k = p & 15;
            As[k][m] = g_ctx[(size_t)(row0 + m) * D + k0 + k];
        }
#pragma unroll
        for (int i = 0; i < 8; i++) {
            int p = t + i * 256;
            int k = p >> 7, n = p & 127;
            Bs[k][n] = Wout[(size_t)(k0 + k) * D + col0 + n];
        }
        __syncthreads();
#pragma unroll
        for (int k = 0; k < BK; k++) {
            float a[8], b[8];
#pragma unroll
            for (int i = 0; i < 8; i++) a[i] = As[k][tm + i];
#pragma unroll
            for (int j = 0; j < 8; j++) b[j] = Bs[k][tn + j];
#pragma unroll
            for (int i = 0; i < 8; i++)
#pragma unroll
                for (int j = 0; j < 8; j++)
                    acc[i][j] = fmaf(a[i], b[j], acc[i][j]);
        }
        __syncthreads();
    }
#pragma unroll
    for (int i = 0; i < 8; i++) {
        const int r = row0 + tm + i;
#pragma unroll
        for (int j = 0; j < 8; j++)
            out[(size_t)r * D + col0 + tn + j] = acc[i][j];
    }
}

// ---------------------------------------------------------------------------
// Force module load before harness mem checkpoints; enable >48KB dyn smem.
// ---------------------------------------------------------------------------
namespace {
struct CudaWarm {
    CudaWarm() {
        cudaFuncSetAttribute(k2_attn,
            cudaFuncAttributeMaxDynamicSharedMemorySize, cfg::SMEM2);
        cudaFuncAttributes a;
        cudaFuncGetAttributes(&a, (const void*)k1_qkv);
        cudaFuncGetAttributes(&a, (const void*)k2_attn);
        cudaFuncGetAttributes(&a, (const void*)k5_out);
    }
};
CudaWarm g_warm;
}

// ---------------------------------------------------------------------------
extern "C" void kernel_launch(void* const* d_in, const int* in_sizes, int n_in,
                              void* d_out, int out_size)
{
    using namespace cfg;
    const float* Zq   = (const float*)d_in[0];
    const float* Zkv  = (const float*)d_in[1];
    const float* mask = (const float*)d_in[2];
    const float* Wqkv = (const float*)d_in[3];
    const float* Wout = (const float*)d_in[4];

    float* out       = (float*)d_out;
    float* attn_mean = out + (size_t)B * S * D;

    cudaFuncSetAttribute(k2_attn,
        cudaFuncAttributeMaxDynamicSharedMemorySize, SMEM2);

    k1_qkv<<<dim3(MROWS / 128, N3 / 128), 256>>>(Zq, Zkv, Wqkv);
    k2_attn<<<dim3(S / TQ, B), 256, SMEM2>>>(mask, attn_mean);
    k5_out<<<dim3(MROWS / 128, D / 128), 256>>>(Wout, out);
}

// round 4
// speedup vs baseline: 1.4049x; 1.4049x over previous
#include <cuda_runtime.h>
#include <math.h>

// ---------------------------------------------------------------------------
// MultiHeadCrossAttentionBlock: B=4, S=2048, D=512, H=8, DK=64
// d_out = out [B,S,D] ++ attn.mean(axis=1) [B,S,S]  (floats, concatenated)
//
// Round 3: k2 rework.
//  * PV micro-tile 4q x 4c x 4k (64 FMA : 8 LDS.128 = 8:1, crossbar-balanced)
//    with 4 k-partial accumulator groups reduced through smem.
//  * Register prefetch (16x LDG.128/thread) of next K/V chunk to hide L2.
//  * Ss row stride padded to 2052 floats (kills 2-way bank conflict on
//    broadcast p-loads whose q-row stride was 2048 floats).
// k1/k5 unchanged (k1 measured at the fp32 SIMT roof already).
// ---------------------------------------------------------------------------

namespace cfg {
constexpr int B  = 4;
constexpr int S  = 2048;
constexpr int D  = 512;
constexpr int H  = 8;
constexpr int DK = 64;
constexpr int N3 = 3 * D;          // 1536
constexpr int MROWS = B * S;       // 8192
constexpr float SCALE = 0.125f;    // DK^-0.5
constexpr int TQ = 16;             // q rows per block
constexpr int TK = 256;            // k/v chunk length
constexpr int NCH = S / TK;        // 8 chunks
constexpr int SROW = S + 4;        // padded Ss row stride (floats)
// dynamic smem: Ss[TQ][SROW] + KVs[64*256] + Qs[DK][20]
constexpr int SMEM2_FLOATS = TQ * SROW + DK * TK + DK * 20;
constexpr int SMEM2 = SMEM2_FLOATS * 4;   // 201,984 bytes
}

// ------------------------------ scratch (64 MB total) ----------------------
__device__ float g_Q [cfg::B * cfg::H * cfg::S * cfg::DK];   // [b,h,s,dk]
__device__ float g_Kt[cfg::B * cfg::H * cfg::DK * cfg::S];   // [b,h,dk,s]
__device__ float g_V [cfg::B * cfg::H * cfg::S * cfg::DK];   // [b,h,s,dk]
__device__ float g_ctx[cfg::B * cfg::S * cfg::D];            // [b,s,h*DK+dk]

// ---------------------------------------------------------------------------
// K1: QKV projection. C[8192,1536] = Z @ Wqkv  (Z = Zq for n<512, else Zkv)
// ---------------------------------------------------------------------------
__global__ __launch_bounds__(256) void k1_qkv(
    const float* __restrict__ Zq, const float* __restrict__ Zkv,
    const float* __restrict__ W)
{
    using namespace cfg;
    constexpr int BM = 128, BN = 128, BK = 16;
    __shared__ float As[BK][BM + 4];
    __shared__ float Bs[BK][BN];

    const int row0 = blockIdx.x * BM;
    const int col0 = blockIdx.y * BN;
    const float* __restrict__ Z = (col0 < D) ? Zq : Zkv;

    const int t  = threadIdx.x;
    const int tm = (t >> 4) << 3;
    const int tn = (t & 15) << 3;

    float acc[8][8];
#pragma unroll
    for (int i = 0; i < 8; i++)
#pragma unroll
        for (int j = 0; j < 8; j++) acc[i][j] = 0.f;

    for (int k0 = 0; k0 < D; k0 += BK) {
#pragma unroll
        for (int i = 0; i < 8; i++) {           // A tile: 128x16
            int p = t + i * 256;
            int m = p >> 4, k = p & 15;
            As[k][m] = Z[(size_t)(row0 + m) * D + k0 + k];
        }
#pragma unroll
        for (int i = 0; i < 8; i++) {           // B tile: 16x128
            int p = t + i * 256;
            int k = p >> 7, n = p & 127;
            Bs[k][n] = W[(size_t)(k0 + k) * N3 + col0 + n];
        }
        __syncthreads();
#pragma unroll
        for (int k = 0; k < BK; k++) {
            float a[8], b[8];
#pragma unroll
            for (int i = 0; i < 8; i++) a[i] = As[k][tm + i];
#pragma unroll
            for (int j = 0; j < 8; j++) b[j] = Bs[k][tn + j];
#pragma unroll
            for (int i = 0; i < 8; i++)
#pragma unroll
                for (int j = 0; j < 8; j++)
                    acc[i][j] = fmaf(a[i], b[j], acc[i][j]);
        }
        __syncthreads();
    }

    const int part = col0 / D;                  // 0=Q, 1=K, 2=V (block-uniform)
#pragma unroll
    for (int i = 0; i < 8; i++) {
        const int r = row0 + tm + i;
        const int b = r >> 11, s = r & (S - 1);
#pragma unroll
        for (int j = 0; j < 8; j++) {
            const int c  = col0 + tn + j - part * D;
            const int h  = c >> 6, dk = c & 63;
            const float v = acc[i][j];
            if (part == 0)      g_Q [((size_t)(b * H + h) * S  + s)  * DK + dk] = v;
            else if (part == 1) g_Kt[((size_t)(b * H + h) * DK + dk) * S  + s ] = v;
            else                g_V [((size_t)(b * H + h) * S  + s)  * DK + dk] = v;
        }
    }
}

// ---------------------------------------------------------------------------
// K2: fused attention. Grid (S/TQ=128, B=4), 256 threads, ~197 KB dyn smem.
// ---------------------------------------------------------------------------
__global__ __launch_bounds__(256, 1) void k2_attn(
    const float* __restrict__ mask, float* __restrict__ attn_out)
{
    using namespace cfg;
    extern __shared__ float sm[];
    float* Ss  = sm;                      // [TQ][SROW]  scores / probs
    float* KVs = Ss + TQ * SROW;          // [64][256] K chunk / [256][64] V chunk / partials
    float* Qs  = KVs + DK * TK;           // [DK][20]    d-major Q tile (padded)

    const int qt = blockIdx.x;
    const int b  = blockIdx.y;
    const int q0 = qt * TQ;
    const int t  = threadIdx.x;

    // score-phase thread coords
    const int qi = t >> 6;                // 0..3  (4 q rows each)
    const int ki = t & 63;                // 0..63 (4 k cols each)
    // pv-phase thread coords
    const int kq  = t >> 6;               // 0..3  k-quarter group
    const int qg4 = ((t >> 4) & 3) << 2;  // q row base (0,4,8,12)
    const int cg4 = (t & 15) << 2;        // col base (0..60)
    // softmax coords
    const int w = t >> 5, lane = t & 31;

    float4 pf[16];                        // prefetch staging registers

    for (int h = 0; h < H; h++) {
        const int bh = b * H + h;
        const float* __restrict__ Qg  = g_Q  + ((size_t)bh * S + q0) * DK;
        const float* __restrict__ Ktg = g_Kt + (size_t)bh * DK * S;
        const float* __restrict__ Vg  = g_V  + (size_t)bh * S * DK;

        // ---- Q tile transposed into smem (16x64 -> [d][q]) ----
#pragma unroll
        for (int i = 0; i < 4; i++) {
            int p = t + i * 256;
            int q = p >> 6, d = p & 63;
            Qs[d * 20 + q] = Qg[q * DK + d];
        }

        // prefetch K chunk 0
#pragma unroll
        for (int i = 0; i < 16; i++) {
            int p4 = t + (i << 8);
            pf[i] = *(const float4*)&Ktg[(size_t)(p4 >> 6) * S + ((p4 & 63) << 2)];
        }

        // ================= QK^T over 8 chunks =================
        for (int c = 0; c < NCH; c++) {
            const int kc = c * TK;
            __syncthreads();              // KVs free (and Qs ordered on c==0)
#pragma unroll
            for (int i = 0; i < 16; i++) {        // stage K chunk c
                int p4 = t + (i << 8);
                *(float4*)&KVs[(p4 >> 6) * TK + ((p4 & 63) << 2)] = pf[i];
            }
            if (c < NCH - 1) {                    // prefetch K chunk c+1
#pragma unroll
                for (int i = 0; i < 16; i++) {
                    int p4 = t + (i << 8);
                    pf[i] = *(const float4*)&Ktg[(size_t)(p4 >> 6) * S + kc + TK + ((p4 & 63) << 2)];
                }
            } else {                              // prefetch V chunk 0
#pragma unroll
                for (int i = 0; i < 16; i++) {
                    int p4 = t + (i << 8);
                    pf[i] = *(const float4*)&Vg[(size_t)(p4 >> 4) * DK + ((p4 & 15) << 2)];
                }
            }
            __syncthreads();

            float acc[4][4];
#pragma unroll
            for (int i = 0; i < 4; i++)
#pragma unroll
                for (int j = 0; j < 4; j++) acc[i][j] = 0.f;

#pragma unroll
            for (int d = 0; d < DK; d++) {
                const float4 kv = *(const float4*)&KVs[d * TK + (ki << 2)];
                const float4 qv = *(const float4*)&Qs[d * 20 + (qi << 2)];
                acc[0][0] = fmaf(qv.x, kv.x, acc[0][0]);
                acc[0][1] = fmaf(qv.x, kv.y, acc[0][1]);
                acc[0][2] = fmaf(qv.x, kv.z, acc[0][2]);
                acc[0][3] = fmaf(qv.x, kv.w, acc[0][3]);
                acc[1][0] = fmaf(qv.y, kv.x, acc[1][0]);
                acc[1][1] = fmaf(qv.y, kv.y, acc[1][1]);
                acc[1][2] = fmaf(qv.y, kv.z, acc[1][2]);
                acc[1][3] = fmaf(qv.y, kv.w, acc[1][3]);
                acc[2][0] = fmaf(qv.z, kv.x, acc[2][0]);
                acc[2][1] = fmaf(qv.z, kv.y, acc[2][1]);
                acc[2][2] = fmaf(qv.z, kv.z, acc[2][2]);
                acc[2][3] = fmaf(qv.z, kv.w, acc[2][3]);
                acc[3][0] = fmaf(qv.w, kv.x, acc[3][0]);
                acc[3][1] = fmaf(qv.w, kv.y, acc[3][1]);
                acc[3][2] = fmaf(qv.w, kv.z, acc[3][2]);
                acc[3][3] = fmaf(qv.w, kv.w, acc[3][3]);
            }

#pragma unroll
            for (int i = 0; i < 4; i++) {         // scores*scale + mask -> Ss
                const int q = (qi << 2) + i;
                const float4 mk = *(const float4*)&mask[(size_t)(q0 + q) * S + kc + (ki << 2)];
                float4 o;
                o.x = fmaf(acc[i][0], SCALE, mk.x);
                o.y = fmaf(acc[i][1], SCALE, mk.y);
                o.z = fmaf(acc[i][2], SCALE, mk.z);
                o.w = fmaf(acc[i][3], SCALE, mk.w);
                *(float4*)&Ss[q * SROW + kc + (ki << 2)] = o;
            }
        }
        __syncthreads();                  // scores complete; KVs consumed

        // stage V chunk 0 (prefetched during last QK chunk)
#pragma unroll
        for (int i = 0; i < 16; i++) {
            int p4 = t + (i << 8);
            *(float4*)&KVs[(p4 >> 4) * DK + ((p4 & 15) << 2)] = pf[i];
        }
        // prefetch V chunk 1
#pragma unroll
        for (int i = 0; i < 16; i++) {
            int p4 = t + (i << 8);
            pf[i] = *(const float4*)&Vg[(size_t)(TK + (p4 >> 4)) * DK + ((p4 & 15) << 2)];
        }

        // ---- softmax + attn_mean RMW: warp w handles rows 2w, 2w+1 ----
#pragma unroll
        for (int rr = 0; rr < 2; rr++) {
            const int q = w * 2 + rr;
            float* row = Ss + q * SROW;
            float m = -1e30f;
            for (int i = lane; i < S; i += 32) m = fmaxf(m, row[i]);
#pragma unroll
            for (int o = 16; o; o >>= 1) m = fmaxf(m, __shfl_xor_sync(0xFFFFFFFFu, m, o));
            float l = 0.f;
            for (int i = lane; i < S; i += 32) {
                float e = __expf(row[i] - m);
                row[i] = e;
                l += e;
            }
#pragma unroll
            for (int o = 16; o; o >>= 1) l += __shfl_xor_sync(0xFFFFFFFFu, l, o);
            const float inv = 1.f / l;

            float* __restrict__ arow = attn_out + ((size_t)b * S + q0 + q) * S;
            for (int i = lane * 4; i < S; i += 128) {
                float4 e = *(float4*)&row[i];
                e.x *= inv; e.y *= inv; e.z *= inv; e.w *= inv;
                *(float4*)&row[i] = e;                 // normalized P back to smem
                float4 a;
                a.x = e.x * 0.125f; a.y = e.y * 0.125f;
                a.z = e.z * 0.125f; a.w = e.w * 0.125f;
                if (h > 0) {
                    float4 prev = *(float4*)&arow[i];
                    a.x += prev.x; a.y += prev.y; a.z += prev.z; a.w += prev.w;
                }
                *(float4*)&arow[i] = a;
            }
        }
        __syncthreads();                  // P normalized; V chunk 0 staged

        // ================= PV over 8 chunks (k-quartered partials) ==========
        float4 cacc[4];
#pragma unroll
        for (int i = 0; i < 4; i++) cacc[i] = make_float4(0.f, 0.f, 0.f, 0.f);

        for (int c = 0; c < NCH; c++) {
            const int vc = c * TK;
            const int kb = vc + (kq << 6);        // this group's 64-k window
#pragma unroll
            for (int kk = 0; kk < 64; kk += 4) {
                const float4 v0 = *(const float4*)&KVs[((kq << 6) + kk + 0) * DK + cg4];
                const float4 v1 = *(const float4*)&KVs[((kq << 6) + kk + 1) * DK + cg4];
                const float4 v2 = *(const float4*)&KVs[((kq << 6) + kk + 2) * DK + cg4];
                const float4 v3 = *(const float4*)&KVs[((kq << 6) + kk + 3) * DK + cg4];
#pragma unroll
                for (int i = 0; i < 4; i++) {
                    const float4 p = *(const float4*)&Ss[(qg4 + i) * SROW + kb + kk];
                    cacc[i].x = fmaf(p.x, v0.x, cacc[i].x);
                    cacc[i].y = fmaf(p.x, v0.y, cacc[i].y);
                    cacc[i].z = fmaf(p.x, v0.z, cacc[i].z);
                    cacc[i].w = fmaf(p.x, v0.w, cacc[i].w);
                    cacc[i].x = fmaf(p.y, v1.x, cacc[i].x);
                    cacc[i].y = fmaf(p.y, v1.y, cacc[i].y);
                    cacc[i].z = fmaf(p.y, v1.z, cacc[i].z);
                    cacc[i].w = fmaf(p.y, v1.w, cacc[i].w);
                    cacc[i].x = fmaf(p.z, v2.x, cacc[i].x);
                    cacc[i].y = fmaf(p.z, v2.y, cacc[i].y);
                    cacc[i].z = fmaf(p.z, v2.z, cacc[i].z);
                    cacc[i].w = fmaf(p.z, v2.w, cacc[i].w);
                    cacc[i].x = fmaf(p.w, v3.x, cacc[i].x);
                    cacc[i].y = fmaf(p.w, v3.y, cacc[i].y);
                    cacc[i].z = fmaf(p.w, v3.z, cacc[i].z);
                    cacc[i].w = fmaf(p.w, v3.w, cacc[i].w);
                }
            }
            if (c < NCH - 1) {
                __syncthreads();                  // chunk c consumed
#pragma unroll
                for (int i = 0; i < 16; i++) {    // stage V chunk c+1
                    int p4 = t + (i << 8);
                    *(float4*)&KVs[(p4 >> 4) * DK + ((p4 & 15) << 2)] = pf[i];
                }
                if (c < NCH - 2) {                // prefetch V chunk c+2
#pragma unroll
                    for (int i = 0; i < 16; i++) {
                        int p4 = t + (i << 8);
                        pf[i] = *(const float4*)&Vg[(size_t)((vc + 2 * TK) + (p4 >> 4)) * DK + ((p4 & 15) << 2)];
                    }
                }
                __syncthreads();
            }
        }

        // ---- reduce the 4 k-quarter partials through smem ----
        __syncthreads();                          // last PV compute done
#pragma unroll
        for (int i = 0; i < 4; i++)
            *(float4*)&KVs[(kq << 10) + (qg4 + i) * DK + cg4] = cacc[i];
        __syncthreads();
        {
            const int q  = t >> 4;                // 0..15
            const int c4 = (t & 15) << 2;
            float4 s0 = *(const float4*)&KVs[0 * 1024 + q * DK + c4];
            float4 s1 = *(const float4*)&KVs[1 * 1024 + q * DK + c4];
            float4 s2 = *(const float4*)&KVs[2 * 1024 + q * DK + c4];
            float4 s3 = *(const float4*)&KVs[3 * 1024 + q * DK + c4];
            float4 o;
            o.x = (s0.x + s1.x) + (s2.x + s3.x);
            o.y = (s0.y + s1.y) + (s2.y + s3.y);
            o.z = (s0.z + s1.z) + (s2.z + s3.z);
            o.w = (s0.w + s1.w) + (s2.w + s3.w);
            *(float4*)&g_ctx[((size_t)b * S + q0 + q) * D + h * DK + c4] = o;
        }
        // next head's first __syncthreads orders KVs reuse
    }
}

// ---------------------------------------------------------------------------
// K5: out[8192,512] = ctx @ Wout.  Same scheme as K1.
// ---------------------------------------------------------------------------
__global__ __launch_bounds__(256) void k5_out(
    const float* __restrict__ Wout, float* __restrict__ out)
{
    using namespace cfg;
    constexpr int BM = 128, BN = 128, BK = 16;
    __shared__ float As[BK][BM + 4];
    __shared__ float Bs[BK][BN];

    const int row0 = blockIdx.x * BM;
    const int col0 = blockIdx.y * BN;
    const int t  = threadIdx.x;
    const int tm = (t >> 4) << 3;
    const int tn = (t & 15) << 3;

    float acc[8][8];
#pragma unroll
    for (int i = 0; i < 8; i++)
#pragma unroll
        for (int j = 0; j < 8; j++) acc[i][j] = 0.f;

    for (int k0 = 0; k0 < D; k0 += BK) {
#pragma unroll
        for (int i = 0; i < 8; i++) {
            int p = t + i * 256;
            int m = p >> 4, k = p & 15;
            As[k][m] = g_ctx[(size_t)(row0 + m) * D + k0 + k];
        }
#pragma unroll
        for (int i = 0; i < 8; i++) {
            int p = t + i * 256;
            int k = p >> 7, n = p & 127;
            Bs[k][n] = Wout[(size_t)(k0 + k) * D + col0 + n];
        }
        __syncthreads();
#pragma unroll
        for (int k = 0; k < BK; k++) {
            float a[8], b[8];
#pragma unroll
            for (int i = 0; i < 8; i++) a[i] = As[k][tm + i];
#pragma unroll
            for (int j = 0; j < 8; j++) b[j] = Bs[k][tn + j];
#pragma unroll
            for (int i = 0; i < 8; i++)
#pragma unroll
                for (int j = 0; j < 8; j++)
                    acc[i][j] = fmaf(a[i], b[j], acc[i][j]);
        }
        __syncthreads();
    }
#pragma unroll
    for (int i = 0; i < 8; i++) {
        const int r = row0 + tm + i;
#pragma unroll
        for (int j = 0; j < 8; j++)
            out[(size_t)r * D + col0 + tn + j] = acc[i][j];
    }
}

// ---------------------------------------------------------------------------
namespace {
struct CudaWarm {
    CudaWarm() {
        cudaFuncSetAttribute(k2_attn,
            cudaFuncAttributeMaxDynamicSharedMemorySize, cfg::SMEM2);
        cudaFuncAttributes a;
        cudaFuncGetAttributes(&a, (const void*)k1_qkv);
        cudaFuncGetAttributes(&a, (const void*)k2_attn);
        cudaFuncGetAttributes(&a, (const void*)k5_out);
    }
};
CudaWarm g_warm;
}

// ---------------------------------------------------------------------------
extern "C" void kernel_launch(void* const* d_in, const int* in_sizes, int n_in,
                              void* d_out, int out_size)
{
    using namespace cfg;
    const float* Zq   = (const float*)d_in[0];
    const float* Zkv  = (const float*)d_in[1];
    const float* mask = (const float*)d_in[2];
    const float* Wqkv = (const float*)d_in[3];
    const float* Wout = (const float*)d_in[4];

    float* out       = (float*)d_out;
    float* attn_mean = out + (size_t)B * S * D;

    cudaFuncSetAttribute(k2_attn,
        cudaFuncAttributeMaxDynamicSharedMemorySize, SMEM2);

    k1_qkv<<<dim3(MROWS / 128, N3 / 128), 256>>>(Zq, Zkv, Wqkv);
    k2_attn<<<dim3(S / TQ, B), 256, SMEM2>>>(mask, attn_mean);
    k5_out<<<dim3(MROWS / 128, D / 128), 256>>>(Wout, out);
}